// round 6
// baseline (speedup 1.0000x reference)
#include <cuda_runtime.h>
#include <cstdint>

#define NUM_USERS 200000
#define NUM_ITEMS 100000
#define N_NODES   (NUM_USERS + NUM_ITEMS)     // users first, then items
#define EMB_DIM   64
#define D2        (EMB_DIM / 2)               // 32 float2 lanes per fp32 row (256 B)
#define MAX_EDGES 3000000

#define SCAN_TPB    1024
#define SCAN_BLOCKS ((N_NODES + SCAN_TPB - 1) / SCAN_TPB)   // 293

// ---------------------------------------------------------------------------
// Scratch (__device__ globals; no allocation allowed)
// ---------------------------------------------------------------------------
__device__ int            g_deg[N_NODES];
__device__ int            g_off[N_NODES];
__device__ int            g_bsum[SCAN_BLOCKS];
__device__ int            g_bbase[SCAN_BLOCKS];
__device__ unsigned short g_rank_s[MAX_EDGES];               // slot in src bucket (6 MB)
__device__ unsigned short g_rank_d[MAX_EDGES];               // slot in dst bucket (6 MB)
__device__ int            g_adj[2 * MAX_EDGES];              // LOCAL neighbor ids, 24 MB
__device__ float          g_x1[(size_t)N_NODES * EMB_DIM];   // x1 fp32, users then items

// ---------------------------------------------------------------------------
// 0. zero degrees (tiny)
// ---------------------------------------------------------------------------
__global__ void k_zerodeg() {
    int t = blockIdx.x * blockDim.x + threadIdx.x;
    int stride = gridDim.x * blockDim.x;
    for (int i = t; i < N_NODES; i += stride) g_deg[i] = 0;
}

// ---------------------------------------------------------------------------
// 1. degree histogram, 4 edges/thread (int4 loads); atomic return = rank
// ---------------------------------------------------------------------------
__global__ void k_count(const int4* __restrict__ src4, const int4* __restrict__ dst4,
                        int num_edges) {
    int q = blockIdx.x * blockDim.x + threadIdx.x;           // quad index
    int nq = num_edges >> 2;
    if (q < nq) {
        int4 s = __ldg(src4 + q);
        int4 d = __ldg(dst4 + q);
        ushort4 rs, rd;
        rs.x = (unsigned short)atomicAdd(&g_deg[s.x], 1);
        rs.y = (unsigned short)atomicAdd(&g_deg[s.y], 1);
        rs.z = (unsigned short)atomicAdd(&g_deg[s.z], 1);
        rs.w = (unsigned short)atomicAdd(&g_deg[s.w], 1);
        rd.x = (unsigned short)atomicAdd(&g_deg[NUM_USERS + d.x], 1);
        rd.y = (unsigned short)atomicAdd(&g_deg[NUM_USERS + d.y], 1);
        rd.z = (unsigned short)atomicAdd(&g_deg[NUM_USERS + d.z], 1);
        rd.w = (unsigned short)atomicAdd(&g_deg[NUM_USERS + d.w], 1);
        reinterpret_cast<ushort4*>(g_rank_s)[q] = rs;
        reinterpret_cast<ushort4*>(g_rank_d)[q] = rd;
    } else if (q == nq) {                                    // tail (num_edges % 4)
        const int* src = reinterpret_cast<const int*>(src4);
        const int* dst = reinterpret_cast<const int*>(dst4);
        for (int e = nq * 4; e < num_edges; e++) {
            g_rank_s[e] = (unsigned short)atomicAdd(&g_deg[src[e]], 1);
            g_rank_d[e] = (unsigned short)atomicAdd(&g_deg[NUM_USERS + dst[e]], 1);
        }
    }
}

// ---------------------------------------------------------------------------
// 2-4. exclusive prefix scan over g_deg -> g_off
// ---------------------------------------------------------------------------
__global__ void k_scan1() {
    __shared__ int sh[SCAN_TPB];
    int tid = threadIdx.x;
    int gid = blockIdx.x * SCAN_TPB + tid;
    int v = (gid < N_NODES) ? g_deg[gid] : 0;
    sh[tid] = v;
    __syncthreads();
    for (int ofs = 1; ofs < SCAN_TPB; ofs <<= 1) {
        int t = 0;
        if (tid >= ofs) t = sh[tid - ofs];
        __syncthreads();
        sh[tid] += t;
        __syncthreads();
    }
    int incl = sh[tid];
    if (gid < N_NODES) g_off[gid] = incl - v;
    if (tid == SCAN_TPB - 1) g_bsum[blockIdx.x] = incl;
}

__global__ void k_scan2() {
    __shared__ int sh[512];
    int tid = threadIdx.x;
    int v = (tid < SCAN_BLOCKS) ? g_bsum[tid] : 0;
    sh[tid] = v;
    __syncthreads();
    for (int ofs = 1; ofs < 512; ofs <<= 1) {
        int t = 0;
        if (tid >= ofs) t = sh[tid - ofs];
        __syncthreads();
        sh[tid] += t;
        __syncthreads();
    }
    if (tid < SCAN_BLOCKS) g_bbase[tid] = sh[tid] - v;
}

__global__ void k_scan3() {
    int gid = blockIdx.x * SCAN_TPB + threadIdx.x;
    if (gid < N_NODES) g_off[gid] += g_bbase[blockIdx.x];
}

// ---------------------------------------------------------------------------
// 5. bin edges into CSR — no atomics, 4 edges/thread.
//    Adjacency stores LOCAL ids: user rows hold item ids, item rows user ids.
// ---------------------------------------------------------------------------
__global__ void k_bin(const int4* __restrict__ src4, const int4* __restrict__ dst4,
                      int num_edges) {
    int q = blockIdx.x * blockDim.x + threadIdx.x;
    int nq = num_edges >> 2;
    if (q < nq) {
        int4 s = __ldg(src4 + q);
        int4 d = __ldg(dst4 + q);
        ushort4 rs = reinterpret_cast<const ushort4*>(g_rank_s)[q];
        ushort4 rd = reinterpret_cast<const ushort4*>(g_rank_d)[q];
        g_adj[__ldg(&g_off[s.x]) + rs.x] = d.x;
        g_adj[__ldg(&g_off[s.y]) + rs.y] = d.y;
        g_adj[__ldg(&g_off[s.z]) + rs.z] = d.z;
        g_adj[__ldg(&g_off[s.w]) + rs.w] = d.w;
        g_adj[__ldg(&g_off[NUM_USERS + d.x]) + rd.x] = s.x;
        g_adj[__ldg(&g_off[NUM_USERS + d.y]) + rd.y] = s.y;
        g_adj[__ldg(&g_off[NUM_USERS + d.z]) + rd.z] = s.z;
        g_adj[__ldg(&g_off[NUM_USERS + d.w]) + rd.w] = s.w;
    } else if (q == nq) {
        const int* src = reinterpret_cast<const int*>(src4);
        const int* dst = reinterpret_cast<const int*>(dst4);
        for (int e = nq * 4; e < num_edges; e++) {
            int s = src[e], d = dst[e];
            g_adj[__ldg(&g_off[s]) + g_rank_s[e]]             = d;
            g_adj[__ldg(&g_off[NUM_USERS + d]) + g_rank_d[e]] = s;
        }
    }
}

// ---------------------------------------------------------------------------
// Warp-level fp32 mean gather: one warp per node, float2/lane (256 B rows),
// unroll 8 -> up to 8 row loads in flight per warp.
// ---------------------------------------------------------------------------
__device__ __forceinline__ float2 gather_mean(int node, int lane,
                                              const float2* __restrict__ tab) {
    int off = g_off[node];
    int deg = g_deg[node];
    float ax = 0.f, ay = 0.f;
    for (int base = 0; base < deg; base += 32) {
        int nidx = 0;
        if (base + lane < deg) nidx = __ldg(&g_adj[off + base + lane]);
        int lim = min(32, deg - base);
        int k = 0;
        for (; k + 8 <= lim; k += 8) {
            int n[8];
            float2 v[8];
#pragma unroll
            for (int j = 0; j < 8; j++) n[j] = __shfl_sync(0xffffffffu, nidx, k + j);
#pragma unroll
            for (int j = 0; j < 8; j++) v[j] = __ldg(&tab[(long)n[j] * D2 + lane]);
#pragma unroll
            for (int j = 0; j < 8; j++) { ax += v[j].x; ay += v[j].y; }
        }
        for (; k < lim; k++) {
            int nb = __shfl_sync(0xffffffffu, nidx, k);
            float2 v = __ldg(&tab[(long)nb * D2 + lane]);
            ax += v.x; ay += v.y;
        }
    }
    float inv = deg > 0 ? 1.f / (float)deg : 0.f;
    return make_float2(ax * inv, ay * inv);
}

// ---------------------------------------------------------------------------
// 6. layer-1 pull: x1[node] = mean of x0 over neighbors (opposite partition)
// ---------------------------------------------------------------------------
__global__ void k_pull1(const float2* __restrict__ u0, const float2* __restrict__ i0) {
    int warp = (blockIdx.x * blockDim.x + threadIdx.x) >> 5;
    int lane = threadIdx.x & 31;
    if (warp >= N_NODES) return;
    bool is_user = warp < NUM_USERS;
    const float2* tab = is_user ? i0 : u0;                    // local ids index this
    float2 m = gather_mean(warp, lane, tab);
    reinterpret_cast<float2*>(g_x1)[(long)warp * D2 + lane] = m;
}

// ---------------------------------------------------------------------------
// 7. layer-2 pull fused with final combine:
//    out[n] = (x0 + x1 + mean_neighbors(x1_other)) / 3
// ---------------------------------------------------------------------------
__global__ void k_pull2(const float2* __restrict__ u0, const float2* __restrict__ i0,
                        float2* __restrict__ out) {
    int warp = (blockIdx.x * blockDim.x + threadIdx.x) >> 5;
    int lane = threadIdx.x & 31;
    if (warp >= N_NODES) return;
    bool is_user = warp < NUM_USERS;

    const float2* x1   = reinterpret_cast<const float2*>(g_x1);
    const float2* tab2 = is_user ? (x1 + (long)NUM_USERS * D2) : x1;  // local ids
    float2 m = gather_mean(warp, lane, tab2);                 // x2

    long idx = (long)warp * D2 + lane;
    const long n_u = (long)NUM_USERS * D2;
    float2 a = (idx < n_u) ? __ldg(&u0[idx]) : __ldg(&i0[idx - n_u]); // x0
    float2 b = x1[idx];                                               // x1

    const float third = 1.0f / 3.0f;
    out[idx] = make_float2((a.x + b.x + m.x) * third, (a.y + b.y + m.y) * third);
}

// ---------------------------------------------------------------------------
// kernel_launch: 8 launches
// ---------------------------------------------------------------------------
extern "C" void kernel_launch(void* const* d_in, const int* in_sizes, int n_in,
                              void* d_out, int out_size) {
    const float2* user_emb = (const float2*)d_in[0];
    const float2* item_emb = (const float2*)d_in[1];
    const int4*   src4     = (const int4*)d_in[2];
    const int4*   dst4     = (const int4*)d_in[3];
    const int     E        = in_sizes[2];
    float2*       out      = (float2*)d_out;

    const int TPB = 256;
    const int quad_blocks = ((E >> 2) + 1 + TPB - 1) / TPB;   // +1 thread for tail
    const long pull_threads = (long)N_NODES * 32;
    const int  pull_blocks  = (int)((pull_threads + TPB - 1) / TPB);

    k_zerodeg<<<256, TPB>>>();
    k_count<<<quad_blocks, TPB>>>(src4, dst4, E);
    k_scan1<<<SCAN_BLOCKS, SCAN_TPB>>>();
    k_scan2<<<1, 512>>>();
    k_scan3<<<SCAN_BLOCKS, SCAN_TPB>>>();
    k_bin<<<quad_blocks, TPB>>>(src4, dst4, E);

    k_pull1<<<pull_blocks, TPB>>>(user_emb, item_emb);
    k_pull2<<<pull_blocks, TPB>>>(user_emb, item_emb, out);
}

// round 7
// speedup vs baseline: 1.0782x; 1.0782x over previous
#include <cuda_runtime.h>
#include <cstdint>

#define NUM_USERS 200000
#define NUM_ITEMS 100000
#define N_NODES   (NUM_USERS + NUM_ITEMS)     // users first, then items
#define EMB_DIM   64
#define D2        (EMB_DIM / 2)               // 32 float2 lanes per fp32 row (256 B)
#define MAX_EDGES 3000000

#define SCAN_TPB    1024
#define SCAN_BLOCKS ((N_NODES + SCAN_TPB - 1) / SCAN_TPB)   // 293

// ---------------------------------------------------------------------------
// Scratch (__device__ globals; zero-initialized at module load; no allocation)
// ---------------------------------------------------------------------------
__device__ int   g_deg[N_NODES];              // self-cleaned by k_pull2
__device__ int   g_off[N_NODES];              // block-local exclusive offsets
__device__ int   g_bsum[SCAN_BLOCKS];
__device__ int   g_bbase[SCAN_BLOCKS];        // scanned block bases
__device__ int   g_ticket;                    // last-block ticket (self-resetting)
__device__ int   g_rank_s[MAX_EDGES];         // slot of edge in src bucket
__device__ int   g_rank_d[MAX_EDGES];         // slot of edge in dst bucket
__device__ int   g_adj[2 * MAX_EDGES];        // LOCAL neighbor ids, 24 MB
__device__ float g_x1[(size_t)N_NODES * EMB_DIM];   // x1 fp32, users then items

// final offset of a node = block-local offset + scanned block base
__device__ __forceinline__ int node_off(int node) {
    return g_off[node] + __ldg(&g_bbase[node >> 10]);
}

// ---------------------------------------------------------------------------
// 1. degree histogram; atomic return value = this edge's slot in the bucket.
//    Requires g_deg == 0 on entry (static init / self-clean by k_pull2).
// ---------------------------------------------------------------------------
__global__ void k_count(const int* __restrict__ src, const int* __restrict__ dst,
                        int num_edges) {
    int e = blockIdx.x * blockDim.x + threadIdx.x;
    if (e >= num_edges) return;
    int s = __ldg(src + e), d = __ldg(dst + e);
    g_rank_s[e] = atomicAdd(&g_deg[s], 1);
    g_rank_d[e] = atomicAdd(&g_deg[NUM_USERS + d], 1);
}

// ---------------------------------------------------------------------------
// 2. block-local exclusive scan of degrees; the LAST block to finish also
//    scans the 293 block sums into g_bbase (and resets the ticket).
// ---------------------------------------------------------------------------
__global__ void k_scan1() {
    __shared__ int sh[SCAN_TPB];
    __shared__ int is_last;
    int tid = threadIdx.x;
    int gid = blockIdx.x * SCAN_TPB + tid;

    int v = (gid < N_NODES) ? g_deg[gid] : 0;
    sh[tid] = v;
    __syncthreads();
    for (int ofs = 1; ofs < SCAN_TPB; ofs <<= 1) {
        int t = 0;
        if (tid >= ofs) t = sh[tid - ofs];
        __syncthreads();
        sh[tid] += t;
        __syncthreads();
    }
    int incl = sh[tid];
    if (gid < N_NODES) g_off[gid] = incl - v;                // block-local exclusive
    if (tid == SCAN_TPB - 1) g_bsum[blockIdx.x] = incl;

    // last-block ticket: fence our g_bsum/g_off writes, then take a ticket
    __threadfence();
    if (tid == 0) is_last = (atomicAdd(&g_ticket, 1) == gridDim.x - 1);
    __syncthreads();

    if (is_last) {
        __threadfence();                                     // acquire other blocks' g_bsum
        int bv = 0;
        if (tid < 512) {
            bv = (tid < SCAN_BLOCKS) ? g_bsum[tid] : 0;
            sh[tid] = bv;
        }
        __syncthreads();
        for (int ofs = 1; ofs < 512; ofs <<= 1) {
            int t = 0;
            if (tid < 512 && tid >= ofs) t = sh[tid - ofs];
            __syncthreads();
            if (tid < 512) sh[tid] += t;
            __syncthreads();
        }
        if (tid < SCAN_BLOCKS) g_bbase[tid] = sh[tid] - bv;  // exclusive base
        if (tid == 0) g_ticket = 0;                          // self-reset for next replay
    }
}

// ---------------------------------------------------------------------------
// 3. bin edges into CSR — no atomics (ranks from k_count), LOCAL neighbor ids
// ---------------------------------------------------------------------------
__global__ void k_bin(const int* __restrict__ src, const int* __restrict__ dst,
                      int num_edges) {
    int e = blockIdx.x * blockDim.x + threadIdx.x;
    if (e >= num_edges) return;
    int s = __ldg(src + e), d = __ldg(dst + e);
    int dn = NUM_USERS + d;
    g_adj[node_off(s)  + g_rank_s[e]] = d;                   // user row -> item local id
    g_adj[node_off(dn) + g_rank_d[e]] = s;                   // item row -> user local id
}

// ---------------------------------------------------------------------------
// Warp-level fp32 mean gather: one warp per node, float2/lane (256 B rows),
// unroll 4 (the R2-proven shape).
// ---------------------------------------------------------------------------
__device__ __forceinline__ float2 gather_mean(int off, int deg, int lane,
                                              const float2* __restrict__ tab) {
    float ax = 0.f, ay = 0.f;
    for (int base = 0; base < deg; base += 32) {
        int nidx = 0;
        if (base + lane < deg) nidx = __ldg(&g_adj[off + base + lane]);
        int lim = min(32, deg - base);
        int k = 0;
        for (; k + 4 <= lim; k += 4) {
            int n0 = __shfl_sync(0xffffffffu, nidx, k);
            int n1 = __shfl_sync(0xffffffffu, nidx, k + 1);
            int n2 = __shfl_sync(0xffffffffu, nidx, k + 2);
            int n3 = __shfl_sync(0xffffffffu, nidx, k + 3);
            float2 v0 = __ldg(&tab[(long)n0 * D2 + lane]);
            float2 v1 = __ldg(&tab[(long)n1 * D2 + lane]);
            float2 v2 = __ldg(&tab[(long)n2 * D2 + lane]);
            float2 v3 = __ldg(&tab[(long)n3 * D2 + lane]);
            ax += v0.x + v1.x + v2.x + v3.x;
            ay += v0.y + v1.y + v2.y + v3.y;
        }
        for (; k < lim; k++) {
            int nb = __shfl_sync(0xffffffffu, nidx, k);
            float2 v = __ldg(&tab[(long)nb * D2 + lane]);
            ax += v.x; ay += v.y;
        }
    }
    float inv = deg > 0 ? 1.f / (float)deg : 0.f;
    return make_float2(ax * inv, ay * inv);
}

// ---------------------------------------------------------------------------
// 4. layer-1 pull: x1[node] = mean of x0 over neighbors (opposite partition)
// ---------------------------------------------------------------------------
__global__ void k_pull1(const float2* __restrict__ u0, const float2* __restrict__ i0) {
    int warp = (blockIdx.x * blockDim.x + threadIdx.x) >> 5;
    int lane = threadIdx.x & 31;
    if (warp >= N_NODES) return;
    bool is_user = warp < NUM_USERS;
    const float2* tab = is_user ? i0 : u0;                   // local ids index this
    int off = node_off(warp);
    int deg = g_deg[warp];
    float2 m = gather_mean(off, deg, lane, tab);
    reinterpret_cast<float2*>(g_x1)[(long)warp * D2 + lane] = m;
}

// ---------------------------------------------------------------------------
// 5. layer-2 pull fused with final combine; self-cleans g_deg for next replay.
//    out[n] = (x0 + x1 + mean_neighbors(x1_other)) / 3
// ---------------------------------------------------------------------------
__global__ void k_pull2(const float2* __restrict__ u0, const float2* __restrict__ i0,
                        float2* __restrict__ out) {
    int warp = (blockIdx.x * blockDim.x + threadIdx.x) >> 5;
    int lane = threadIdx.x & 31;
    if (warp >= N_NODES) return;
    bool is_user = warp < NUM_USERS;

    const float2* x1   = reinterpret_cast<const float2*>(g_x1);
    const float2* tab2 = is_user ? (x1 + (long)NUM_USERS * D2) : x1;  // local ids
    int off = node_off(warp);
    int deg = g_deg[warp];
    float2 m = gather_mean(off, deg, lane, tab2);            // x2

    long idx = (long)warp * D2 + lane;
    const long n_u = (long)NUM_USERS * D2;
    float2 a = (idx < n_u) ? __ldg(&u0[idx]) : __ldg(&i0[idx - n_u]); // x0
    float2 b = x1[idx];                                               // x1

    const float third = 1.0f / 3.0f;
    out[idx] = make_float2((a.x + b.x + m.x) * third, (a.y + b.y + m.y) * third);

    if (lane == 0) g_deg[warp] = 0;                          // self-clean for next run
}

// ---------------------------------------------------------------------------
// kernel_launch: 5 launches (pull1 is launch #4 -> lands in the ncu capture slot)
// ---------------------------------------------------------------------------
extern "C" void kernel_launch(void* const* d_in, const int* in_sizes, int n_in,
                              void* d_out, int out_size) {
    const float2* user_emb = (const float2*)d_in[0];
    const float2* item_emb = (const float2*)d_in[1];
    const int*    src      = (const int*)d_in[2];
    const int*    dst      = (const int*)d_in[3];
    const int     E        = in_sizes[2];
    float2*       out      = (float2*)d_out;

    const int TPB = 256;
    const int edge_blocks = (E + TPB - 1) / TPB;
    const long pull_threads = (long)N_NODES * 32;
    const int  pull_blocks  = (int)((pull_threads + TPB - 1) / TPB);

    k_count<<<edge_blocks, TPB>>>(src, dst, E);
    k_scan1<<<SCAN_BLOCKS, SCAN_TPB>>>();
    k_bin<<<edge_blocks, TPB>>>(src, dst, E);
    k_pull1<<<pull_blocks, TPB>>>(user_emb, item_emb);
    k_pull2<<<pull_blocks, TPB>>>(user_emb, item_emb, out);
}